// round 11
// baseline (speedup 1.0000x reference)
#include <cuda_runtime.h>
#include <stdint.h>

#define NN      1000000
#define KTOP    10000
#define NB      8192
#define BSHIFT  19
#define DH      128
#define EPS     1e-5f
#define TIE_MAX 1024
#define SMAX    60

// ---------------- scratch (__device__ globals; no allocation allowed) -------
__device__ float    g_speed2[NN];     // 4 MB, L2-resident
__device__ unsigned g_hist[NB];
__device__ int      g_cand[NN];       // worst-case safe candidate list
__device__ int      g_cand_cnt;
__device__ float    g_sums[8];        // hv_feat[3], hv_wpos[3], hv_mpos[2]
__device__ int      g_B;              // boundary bucket
__device__ int      g_needed;         // how many still needed from bucket B
__device__ float    g_hout[SMAX][DH]; // MLP result, added to out at the end

// ---------------- K0: zero the per-replay state -----------------------------
__global__ void k_zero() {
    int i = blockIdx.x * blockDim.x + threadIdx.x;
    if (i < NB) g_hist[i] = 0u;
    if (i < 8)  g_sums[i] = 0.f;
    if (i == 0) g_cand_cnt = 0;
}

// ---------------- K1: speed2 + 8192-bucket histogram ------------------------
__global__ void k_speed2_hist(const float* __restrict__ nf) {
    __shared__ unsigned sh[NB];
    for (int j = threadIdx.x; j < NB; j += blockDim.x) sh[j] = 0u;
    __syncthreads();
    int stride = gridDim.x * blockDim.x;
    for (int i = blockIdx.x * blockDim.x + threadIdx.x; i < NN; i += stride) {
        float4 v = *reinterpret_cast<const float4*>(nf + (size_t)i * 12);
        float s = __fadd_rn(__fadd_rn(__fmul_rn(v.x, v.x), __fmul_rn(v.y, v.y)),
                            __fmul_rn(v.z, v.z));
        g_speed2[i] = s;
        atomicAdd(&sh[__float_as_uint(s) >> BSHIFT], 1u);
    }
    __syncthreads();
    for (int j = threadIdx.x; j < NB; j += blockDim.x)
        if (sh[j]) atomicAdd(&g_hist[j], sh[j]);
}

// ---------------- K2: find boundary bucket (1 block) ------------------------
__global__ void k_find_bucket() {
    __shared__ unsigned partial[1024];
    int t = threadIdx.x;
    unsigned s = 0;
    #pragma unroll
    for (int j = 0; j < 8; j++) s += g_hist[NB - 1 - (t * 8 + j)];
    partial[t] = s;
    __syncthreads();
    if (t == 0) {
        unsigned cum = 0;
        for (int c = 0; c < 1024; c++) {
            unsigned p = partial[c];
            if (cum + p >= (unsigned)KTOP) {
                for (int j = 0; j < 8; j++) {
                    int b = NB - 1 - (c * 8 + j);
                    unsigned h = g_hist[b];
                    if (cum + h >= (unsigned)KTOP) {
                        g_B = b;
                        g_needed = KTOP - (int)cum;
                        return;
                    }
                    cum += h;
                }
            }
            cum += p;
        }
    }
}

// ---------------- K3: sum features above bucket B, collect bucket-B cands ---
__global__ void k_sum_and_cand(const float* __restrict__ nf,
                               const float* __restrict__ wp,
                               const float* __restrict__ mp) {
    int B = g_B;
    float a[8];
    #pragma unroll
    for (int c = 0; c < 8; c++) a[c] = 0.f;
    int stride = gridDim.x * blockDim.x;
    const float4* sp4 = reinterpret_cast<const float4*>(g_speed2);
    for (int q = blockIdx.x * blockDim.x + threadIdx.x; q < NN / 4; q += stride) {
        float4 s4 = sp4[q];   // L2-resident
        float sv[4] = {s4.x, s4.y, s4.z, s4.w};
        #pragma unroll
        for (int u = 0; u < 4; u++) {
            int b = (int)(__float_as_uint(sv[u]) >> BSHIFT);
            if (b < B) continue;
            int i = q * 4 + u;
            if (b > B) {
                float4 v = *reinterpret_cast<const float4*>(nf + (size_t)i * 12);
                a[0] += v.x; a[1] += v.y; a[2] += v.z;
                a[3] += wp[(size_t)i * 3];     a[4] += wp[(size_t)i * 3 + 1];
                a[5] += wp[(size_t)i * 3 + 2];
                a[6] += mp[(size_t)i * 2];     a[7] += mp[(size_t)i * 2 + 1];
            } else {
                g_cand[atomicAdd(&g_cand_cnt, 1)] = i;
            }
        }
    }
    #pragma unroll
    for (int o = 16; o; o >>= 1)
        #pragma unroll
        for (int c = 0; c < 8; c++) a[c] += __shfl_xor_sync(0xFFFFFFFFu, a[c], o);
    __shared__ float ws[16][8];
    int wid = threadIdx.x >> 5;
    if ((threadIdx.x & 31) == 0)
        for (int c = 0; c < 8; c++) ws[wid][c] = a[c];
    __syncthreads();
    if (threadIdx.x < 8) {
        float s = 0.f;
        int nw = blockDim.x >> 5;
        for (int w = 0; w < nw; w++) s += ws[w][threadIdx.x];
        atomicAdd(&g_sums[threadIdx.x], s);
    }
}

// ---------------- K4: exact in-bucket selection + boundary sums (1 block) ---
__global__ void k_finalize(const float* __restrict__ nf,
                           const float* __restrict__ wp,
                           const float* __restrict__ mp) {
    __shared__ unsigned sh[256];
    __shared__ int s_tie[TIE_MAX];
    __shared__ int s_tiecnt;
    __shared__ unsigned s_pv;
    __shared__ int s_kneed;
    int tid = threadIdx.x;
    int C = g_cand_cnt;
    if (tid == 0) { s_pv = 0u; s_kneed = g_needed; s_tiecnt = 0; }
    __syncthreads();

    unsigned pm = 0u;
    const int shifts[3] = {11, 3, 0};
    const int widths[3] = {256, 256, 8};
    for (int p = 0; p < 3; p++) {
        int sft = shifts[p], w = widths[p];
        for (int j = tid; j < w; j += blockDim.x) sh[j] = 0u;
        __syncthreads();
        unsigned pv = s_pv;
        for (int i = tid; i < C; i += blockDim.x) {
            unsigned u = __float_as_uint(g_speed2[g_cand[i]]) & 0x7FFFFu;
            if ((u & pm) == pv) atomicAdd(&sh[(u >> sft) & (unsigned)(w - 1)], 1u);
        }
        __syncthreads();
        if (tid == 0) {
            unsigned cum = 0;
            int kn = s_kneed;
            for (int d = w - 1; d >= 0; d--) {
                unsigned c = sh[d];
                if (cum + c >= (unsigned)kn) {
                    s_pv = pv | ((unsigned)d << sft);
                    s_kneed = kn - (int)cum;
                    break;
                }
                cum += c;
            }
        }
        pm |= (unsigned)(widths[p] - 1) << shifts[p];
        __syncthreads();
    }
    unsigned tl = s_pv;

    float a[8];
    #pragma unroll
    for (int c = 0; c < 8; c++) a[c] = 0.f;
    for (int i = tid; i < C; i += blockDim.x) {
        int idx = g_cand[i];
        unsigned u = __float_as_uint(g_speed2[idx]) & 0x7FFFFu;
        if (u > tl) {
            float4 v = *reinterpret_cast<const float4*>(nf + (size_t)idx * 12);
            a[0] += v.x; a[1] += v.y; a[2] += v.z;
            a[3] += wp[(size_t)idx * 3];     a[4] += wp[(size_t)idx * 3 + 1];
            a[5] += wp[(size_t)idx * 3 + 2];
            a[6] += mp[(size_t)idx * 2];     a[7] += mp[(size_t)idx * 2 + 1];
        } else if (u == tl) {
            int pos = atomicAdd(&s_tiecnt, 1);
            if (pos < TIE_MAX) s_tie[pos] = idx;
        }
    }
    #pragma unroll
    for (int o = 16; o; o >>= 1)
        #pragma unroll
        for (int c = 0; c < 8; c++) a[c] += __shfl_xor_sync(0xFFFFFFFFu, a[c], o);
    __shared__ float ws[8][8];
    int wid = tid >> 5;
    if ((tid & 31) == 0)
        for (int c = 0; c < 8; c++) ws[wid][c] = a[c];
    __syncthreads();

    if (tid == 0) {
        float sums[8];
        for (int c = 0; c < 8; c++) {
            float s = 0.f;
            for (int w = 0; w < 8; w++) s += ws[w][c];
            sums[c] = s;
        }
        int e = min(s_tiecnt, TIE_MAX);
        int kn = s_kneed;
        int last = -1;
        for (int n = 0; n < kn; n++) {
            int m = 0x7FFFFFFF;
            for (int i = 0; i < e; i++) {
                int v = s_tie[i];
                if (v > last && v < m) m = v;
            }
            if (m == 0x7FFFFFFF) break;
            last = m;
            float4 v = *reinterpret_cast<const float4*>(nf + (size_t)m * 12);
            sums[0] += v.x; sums[1] += v.y; sums[2] += v.z;
            sums[3] += wp[(size_t)m * 3];     sums[4] += wp[(size_t)m * 3 + 1];
            sums[5] += wp[(size_t)m * 3 + 2];
            sums[6] += mp[(size_t)m * 2];     sums[7] += mp[(size_t)m * 2 + 1];
        }
        for (int c = 0; c < 8; c++) g_sums[c] += sums[c];
    }
}

// ---------------- K5: bulk-TMA copy; reads evict_first, writes evict_last ---
#define CHUNK      32768
#define COPY_GRID  444          // 3 blocks/SM * 148 SMs
#define COPY_SMEM  (2 * CHUNK + 128)

__device__ __forceinline__ uint32_t s2u(const void* p) {
    uint32_t a;
    asm("{ .reg .u64 t; cvta.to.shared.u64 t, %1; cvt.u32.u64 %0, t; }"
        : "=r"(a) : "l"(p));
    return a;
}

__global__ void __launch_bounds__(32) k_copy_tma(const char* __restrict__ src,
                                                 char* __restrict__ dst,
                                                 long long nch) {
    extern __shared__ __align__(128) char sm[];
    if (threadIdx.x != 0) return;
    uint32_t base = s2u(sm);
    uint32_t bufs[2] = {base, base + CHUNK};
    uint32_t mbs[2]  = {base + 2 * CHUNK, base + 2 * CHUNK + 8};
    asm volatile("mbarrier.init.shared.b64 [%0], 1;" :: "r"(mbs[0]) : "memory");
    asm volatile("mbarrier.init.shared.b64 [%0], 1;" :: "r"(mbs[1]) : "memory");
    asm volatile("fence.proxy.async.shared::cta;" ::: "memory");

    // Read stream: evict_first (don't pollute L2).
    // Write stream: evict_last (dirty out-lines persist across graph replays;
    // the resident fraction is re-written in L2 next replay with NO DRAM
    // writeback in steady state).
    uint64_t polR, polW;
    asm volatile("createpolicy.fractional.L2::evict_first.b64 %0, 1.0;"
                 : "=l"(polR));
    asm volatile("createpolicy.fractional.L2::evict_last.b64 %0, 1.0;"
                 : "=l"(polW));

    long long step = gridDim.x;
    long long c = blockIdx.x;
    int ph[2] = {0, 0};
    int s = 0;

    if (c < nch) {
        asm volatile("mbarrier.arrive.expect_tx.shared.b64 _, [%0], %1;"
                     :: "r"(mbs[0]), "r"((unsigned)CHUNK) : "memory");
        asm volatile(
            "cp.async.bulk.shared::cta.global.mbarrier::complete_tx::bytes"
            ".L2::cache_hint [%0], [%1], %2, [%3], %4;"
            :: "r"(bufs[0]), "l"(src + c * CHUNK), "r"((unsigned)CHUNK),
               "r"(mbs[0]), "l"(polR) : "memory");
    }
    for (; c < nch; c += step) {
        asm volatile(
            "{\n\t.reg .pred p;\n"
            "WL_%=:\n\t"
            "mbarrier.try_wait.parity.shared.b64 p, [%0], %1;\n\t"
            "@p bra WD_%=;\n\t"
            "bra WL_%=;\n"
            "WD_%=:\n\t}"
            :: "r"(mbs[s]), "r"((unsigned)ph[s]) : "memory");
        ph[s] ^= 1;

        asm volatile(
            "cp.async.bulk.global.shared::cta.bulk_group.L2::cache_hint "
            "[%0], [%1], %2, %3;"
            :: "l"(dst + c * CHUNK), "r"(bufs[s]), "r"((unsigned)CHUNK),
               "l"(polW) : "memory");
        asm volatile("cp.async.bulk.commit_group;" ::: "memory");
        // .read: release once the other buffer's SMEM is drained (not when its
        // global write completes).
        asm volatile("cp.async.bulk.wait_group.read 1;" ::: "memory");

        long long nxt = c + step;
        if (nxt < nch) {
            asm volatile("mbarrier.arrive.expect_tx.shared.b64 _, [%0], %1;"
                         :: "r"(mbs[s ^ 1]), "r"((unsigned)CHUNK) : "memory");
            asm volatile(
                "cp.async.bulk.shared::cta.global.mbarrier::complete_tx::bytes"
                ".L2::cache_hint [%0], [%1], %2, [%3], %4;"
                :: "r"(bufs[s ^ 1]), "l"(src + nxt * CHUNK),
                   "r"((unsigned)CHUNK), "r"(mbs[s ^ 1]), "l"(polR) : "memory");
        }
        s ^= 1;
    }
    asm volatile("cp.async.bulk.wait_group 0;" ::: "memory");
}

// ---------------- K6: build x, LN0, 3-layer MLP, LNf -> g_hout --------------
__global__ void k_mlp_compute(const float* __restrict__ nf,
                              const float* __restrict__ wp,
                              const float* __restrict__ mp,
                              const int* __restrict__ ridx,
                              const float* __restrict__ ln0s, const float* __restrict__ ln0b,
                              const float* __restrict__ w1, const float* __restrict__ b1,
                              const float* __restrict__ w2, const float* __restrict__ b2,
                              const float* __restrict__ w3, const float* __restrict__ b3,
                              const float* __restrict__ lnfs, const float* __restrict__ lnfb) {
    __shared__ float xs[17];
    __shared__ float h[DH];
    __shared__ float red1[4], red2[4];
    __shared__ float s_mu, s_rs;
    int j = threadIdx.x;
    int idx = ridx[blockIdx.x];

    if (j < 17) {
        float v;
        if (j < 9)       v = g_sums[j % 3];
        else if (j < 12) v = nf[(size_t)idx * 12 + (j - 9)];
        else if (j < 15) v = wp[(size_t)idx * 3 + (j - 12)] - g_sums[3 + (j - 12)];
        else             v = mp[(size_t)idx * 2 + (j - 15)] - g_sums[6 + (j - 15)];
        xs[j] = v;
    }
    __syncthreads();
    if (j == 0) {
        float mu = 0.f;
        for (int k = 0; k < 17; k++) mu += xs[k];
        mu /= 17.f;
        float var = 0.f;
        for (int k = 0; k < 17; k++) { float d = xs[k] - mu; var += d * d; }
        var /= 17.f;
        s_mu = mu; s_rs = rsqrtf(var + EPS);
    }
    __syncthreads();
    if (j < 17) xs[j] = (xs[j] - s_mu) * s_rs * ln0s[j] + ln0b[j];
    __syncthreads();

    float acc = b1[j];
    #pragma unroll
    for (int k = 0; k < 17; k++) acc = fmaf(xs[k], w1[k * DH + j], acc);
    acc = fmaxf(acc, 0.f);
    h[j] = acc;
    __syncthreads();

    acc = b2[j];
    #pragma unroll 8
    for (int k = 0; k < DH; k++) acc = fmaf(h[k], w2[k * DH + j], acc);
    acc = fmaxf(acc, 0.f);
    __syncthreads();
    h[j] = acc;
    __syncthreads();

    acc = b3[j];
    #pragma unroll 8
    for (int k = 0; k < DH; k++) acc = fmaf(h[k], w3[k * DH + j], acc);

    float s1 = acc, s2 = acc * acc;
    #pragma unroll
    for (int o = 16; o; o >>= 1) {
        s1 += __shfl_xor_sync(0xFFFFFFFFu, s1, o);
        s2 += __shfl_xor_sync(0xFFFFFFFFu, s2, o);
    }
    if ((j & 31) == 0) { red1[j >> 5] = s1; red2[j >> 5] = s2; }
    __syncthreads();
    float mu = (red1[0] + red1[1] + red1[2] + red1[3]) * (1.f / 128.f);
    float m2 = (red2[0] + red2[1] + red2[2] + red2[3]) * (1.f / 128.f);
    float var = m2 - mu * mu;
    g_hout[blockIdx.x][j] = (acc - mu) * rsqrtf(var + EPS) * lnfs[j] + lnfb[j];
}

// ---------------- K7: tiny tail — out[ridx] += g_hout -----------------------
__global__ void k_add(const int* __restrict__ ridx, float* __restrict__ out) {
    int j = threadIdx.x;
    int idx = ridx[blockIdx.x];
    out[(size_t)idx * DH + j] += g_hout[blockIdx.x][j];
}

// ---------------- launch ----------------------------------------------------
extern "C" void kernel_launch(void* const* d_in, const int* in_sizes, int n_in,
                              void* d_out, int out_size) {
    const float* nf   = (const float*)d_in[0];
    const float* wp   = (const float*)d_in[1];
    const float* mp   = (const float*)d_in[2];
    const float* lat  = (const float*)d_in[3];
    const int*   ridx = (const int*)  d_in[4];
    const float* ln0s = (const float*)d_in[5];
    const float* ln0b = (const float*)d_in[6];
    const float* w1   = (const float*)d_in[7];
    const float* b1   = (const float*)d_in[8];
    const float* w2   = (const float*)d_in[9];
    const float* b2   = (const float*)d_in[10];
    const float* w3   = (const float*)d_in[11];
    const float* b3   = (const float*)d_in[12];
    const float* lnfs = (const float*)d_in[13];
    const float* lnfb = (const float*)d_in[14];
    float* out = (float*)d_out;
    int S = in_sizes[4];

    static cudaStream_t s_side = nullptr;
    static cudaEvent_t  s_fork = nullptr, s_join = nullptr;
    if (s_side == nullptr) {
        cudaStreamCreateWithFlags(&s_side, cudaStreamNonBlocking);
        cudaEventCreateWithFlags(&s_fork, cudaEventDisableTiming);
        cudaEventCreateWithFlags(&s_join, cudaEventDisableTiming);
        cudaFuncSetAttribute(k_copy_tma,
                             cudaFuncAttributeMaxDynamicSharedMemorySize,
                             COPY_SMEM);
    }

    cudaEventRecord(s_fork, 0);
    cudaStreamWaitEvent(s_side, s_fork, 0);

    // Side stream: selection chain + full MLP compute (hidden under the copy).
    k_zero<<<(NB + 255) / 256, 256, 0, s_side>>>();
    k_speed2_hist<<<296, 512, 0, s_side>>>(nf);
    k_find_bucket<<<1, 1024, 0, s_side>>>();
    k_sum_and_cand<<<296, 512, 0, s_side>>>(nf, wp, mp);
    k_finalize<<<1, 256, 0, s_side>>>(nf, wp, mp);
    k_mlp_compute<<<S, DH, 0, s_side>>>(nf, wp, mp, ridx, ln0s, ln0b,
                                        w1, b1, w2, b2, w3, b3, lnfs, lnfb);
    cudaEventRecord(s_join, s_side);

    // Main stream: all-TMA copy (512e6 bytes = 15625 x 32KB chunks exactly).
    long long total = (long long)NN * DH * sizeof(float);
    k_copy_tma<<<COPY_GRID, 32, COPY_SMEM>>>((const char*)lat, (char*)out,
                                             total / CHUNK);

    // Tail: only the 60-row add remains after the copy.
    cudaStreamWaitEvent(0, s_join, 0);
    k_add<<<S, DH>>>(ridx, out);
}

// round 12
// speedup vs baseline: 1.0454x; 1.0454x over previous
#include <cuda_runtime.h>
#include <stdint.h>

#define NN      1000000
#define KTOP    10000
#define NB      8192
#define BSHIFT  19
#define DH      128
#define EPS     1e-5f
#define TIE_MAX 1024
#define SMAX    60

// ---------------- scratch (__device__ globals; no allocation allowed) -------
__device__ float    g_speed2[NN];     // 4 MB, L2-resident
__device__ unsigned g_hist[NB];
__device__ int      g_cand[NN];       // worst-case safe candidate list
__device__ int      g_cand_cnt;
__device__ float    g_sums[8];        // hv_feat[3], hv_wpos[3], hv_mpos[2]
__device__ int      g_B;              // boundary bucket
__device__ int      g_needed;         // how many still needed from bucket B
__device__ float    g_hout[SMAX][DH]; // MLP result, added to out at the end

// ---------------- K0: zero the per-replay state -----------------------------
__global__ void k_zero() {
    int i = blockIdx.x * blockDim.x + threadIdx.x;
    if (i < NB) g_hist[i] = 0u;
    if (i < 8)  g_sums[i] = 0.f;
    if (i == 0) g_cand_cnt = 0;
}

// ---------------- K1: speed2 + 8192-bucket histogram ------------------------
__global__ void k_speed2_hist(const float* __restrict__ nf) {
    __shared__ unsigned sh[NB];
    for (int j = threadIdx.x; j < NB; j += blockDim.x) sh[j] = 0u;
    __syncthreads();
    int stride = gridDim.x * blockDim.x;
    for (int i = blockIdx.x * blockDim.x + threadIdx.x; i < NN; i += stride) {
        float4 v = *reinterpret_cast<const float4*>(nf + (size_t)i * 12);
        float s = __fadd_rn(__fadd_rn(__fmul_rn(v.x, v.x), __fmul_rn(v.y, v.y)),
                            __fmul_rn(v.z, v.z));
        g_speed2[i] = s;
        atomicAdd(&sh[__float_as_uint(s) >> BSHIFT], 1u);
    }
    __syncthreads();
    for (int j = threadIdx.x; j < NB; j += blockDim.x)
        if (sh[j]) atomicAdd(&g_hist[j], sh[j]);
}

// ---------------- K2: find boundary bucket (1 block) ------------------------
__global__ void k_find_bucket() {
    __shared__ unsigned partial[1024];
    int t = threadIdx.x;
    unsigned s = 0;
    #pragma unroll
    for (int j = 0; j < 8; j++) s += g_hist[NB - 1 - (t * 8 + j)];
    partial[t] = s;
    __syncthreads();
    if (t == 0) {
        unsigned cum = 0;
        for (int c = 0; c < 1024; c++) {
            unsigned p = partial[c];
            if (cum + p >= (unsigned)KTOP) {
                for (int j = 0; j < 8; j++) {
                    int b = NB - 1 - (c * 8 + j);
                    unsigned h = g_hist[b];
                    if (cum + h >= (unsigned)KTOP) {
                        g_B = b;
                        g_needed = KTOP - (int)cum;
                        return;
                    }
                    cum += h;
                }
            }
            cum += p;
        }
    }
}

// ---------------- K3: sum features above bucket B, collect bucket-B cands ---
__global__ void k_sum_and_cand(const float* __restrict__ nf,
                               const float* __restrict__ wp,
                               const float* __restrict__ mp) {
    int B = g_B;
    float a[8];
    #pragma unroll
    for (int c = 0; c < 8; c++) a[c] = 0.f;
    int stride = gridDim.x * blockDim.x;
    const float4* sp4 = reinterpret_cast<const float4*>(g_speed2);
    for (int q = blockIdx.x * blockDim.x + threadIdx.x; q < NN / 4; q += stride) {
        float4 s4 = sp4[q];   // L2-resident
        float sv[4] = {s4.x, s4.y, s4.z, s4.w};
        #pragma unroll
        for (int u = 0; u < 4; u++) {
            int b = (int)(__float_as_uint(sv[u]) >> BSHIFT);
            if (b < B) continue;
            int i = q * 4 + u;
            if (b > B) {
                float4 v = *reinterpret_cast<const float4*>(nf + (size_t)i * 12);
                a[0] += v.x; a[1] += v.y; a[2] += v.z;
                a[3] += wp[(size_t)i * 3];     a[4] += wp[(size_t)i * 3 + 1];
                a[5] += wp[(size_t)i * 3 + 2];
                a[6] += mp[(size_t)i * 2];     a[7] += mp[(size_t)i * 2 + 1];
            } else {
                g_cand[atomicAdd(&g_cand_cnt, 1)] = i;
            }
        }
    }
    #pragma unroll
    for (int o = 16; o; o >>= 1)
        #pragma unroll
        for (int c = 0; c < 8; c++) a[c] += __shfl_xor_sync(0xFFFFFFFFu, a[c], o);
    __shared__ float ws[16][8];
    int wid = threadIdx.x >> 5;
    if ((threadIdx.x & 31) == 0)
        for (int c = 0; c < 8; c++) ws[wid][c] = a[c];
    __syncthreads();
    if (threadIdx.x < 8) {
        float s = 0.f;
        int nw = blockDim.x >> 5;
        for (int w = 0; w < nw; w++) s += ws[w][threadIdx.x];
        atomicAdd(&g_sums[threadIdx.x], s);
    }
}

// ---------------- K4: exact in-bucket selection + boundary sums (1 block) ---
__global__ void k_finalize(const float* __restrict__ nf,
                           const float* __restrict__ wp,
                           const float* __restrict__ mp) {
    __shared__ unsigned sh[256];
    __shared__ int s_tie[TIE_MAX];
    __shared__ int s_tiecnt;
    __shared__ unsigned s_pv;
    __shared__ int s_kneed;
    int tid = threadIdx.x;
    int C = g_cand_cnt;
    if (tid == 0) { s_pv = 0u; s_kneed = g_needed; s_tiecnt = 0; }
    __syncthreads();

    unsigned pm = 0u;
    const int shifts[3] = {11, 3, 0};
    const int widths[3] = {256, 256, 8};
    for (int p = 0; p < 3; p++) {
        int sft = shifts[p], w = widths[p];
        for (int j = tid; j < w; j += blockDim.x) sh[j] = 0u;
        __syncthreads();
        unsigned pv = s_pv;
        for (int i = tid; i < C; i += blockDim.x) {
            unsigned u = __float_as_uint(g_speed2[g_cand[i]]) & 0x7FFFFu;
            if ((u & pm) == pv) atomicAdd(&sh[(u >> sft) & (unsigned)(w - 1)], 1u);
        }
        __syncthreads();
        if (tid == 0) {
            unsigned cum = 0;
            int kn = s_kneed;
            for (int d = w - 1; d >= 0; d--) {
                unsigned c = sh[d];
                if (cum + c >= (unsigned)kn) {
                    s_pv = pv | ((unsigned)d << sft);
                    s_kneed = kn - (int)cum;
                    break;
                }
                cum += c;
            }
        }
        pm |= (unsigned)(widths[p] - 1) << shifts[p];
        __syncthreads();
    }
    unsigned tl = s_pv;

    float a[8];
    #pragma unroll
    for (int c = 0; c < 8; c++) a[c] = 0.f;
    for (int i = tid; i < C; i += blockDim.x) {
        int idx = g_cand[i];
        unsigned u = __float_as_uint(g_speed2[idx]) & 0x7FFFFu;
        if (u > tl) {
            float4 v = *reinterpret_cast<const float4*>(nf + (size_t)idx * 12);
            a[0] += v.x; a[1] += v.y; a[2] += v.z;
            a[3] += wp[(size_t)idx * 3];     a[4] += wp[(size_t)idx * 3 + 1];
            a[5] += wp[(size_t)idx * 3 + 2];
            a[6] += mp[(size_t)idx * 2];     a[7] += mp[(size_t)idx * 2 + 1];
        } else if (u == tl) {
            int pos = atomicAdd(&s_tiecnt, 1);
            if (pos < TIE_MAX) s_tie[pos] = idx;
        }
    }
    #pragma unroll
    for (int o = 16; o; o >>= 1)
        #pragma unroll
        for (int c = 0; c < 8; c++) a[c] += __shfl_xor_sync(0xFFFFFFFFu, a[c], o);
    __shared__ float ws[8][8];
    int wid = tid >> 5;
    if ((tid & 31) == 0)
        for (int c = 0; c < 8; c++) ws[wid][c] = a[c];
    __syncthreads();

    if (tid == 0) {
        float sums[8];
        for (int c = 0; c < 8; c++) {
            float s = 0.f;
            for (int w = 0; w < 8; w++) s += ws[w][c];
            sums[c] = s;
        }
        int e = min(s_tiecnt, TIE_MAX);
        int kn = s_kneed;
        int last = -1;
        for (int n = 0; n < kn; n++) {
            int m = 0x7FFFFFFF;
            for (int i = 0; i < e; i++) {
                int v = s_tie[i];
                if (v > last && v < m) m = v;
            }
            if (m == 0x7FFFFFFF) break;
            last = m;
            float4 v = *reinterpret_cast<const float4*>(nf + (size_t)m * 12);
            sums[0] += v.x; sums[1] += v.y; sums[2] += v.z;
            sums[3] += wp[(size_t)m * 3];     sums[4] += wp[(size_t)m * 3 + 1];
            sums[5] += wp[(size_t)m * 3 + 2];
            sums[6] += mp[(size_t)m * 2];     sums[7] += mp[(size_t)m * 2 + 1];
        }
        for (int c = 0; c < 8; c++) g_sums[c] += sums[c];
    }
}

// ---------------- K5: bulk-TMA copy, 4-buffer ring, 2 loads in flight -------
#define CHUNK      16384
#define NBUF       4
#define COPY_GRID  444          // 3 blocks/SM * 148 SMs (4*16KB = 64KB/block)
#define COPY_SMEM  (NBUF * CHUNK + 256)

__device__ __forceinline__ uint32_t s2u(const void* p) {
    uint32_t a;
    asm("{ .reg .u64 t; cvta.to.shared.u64 t, %1; cvt.u32.u64 %0, t; }"
        : "=r"(a) : "l"(p));
    return a;
}

__device__ __forceinline__ void tma_load(uint32_t buf, const char* g,
                                         uint32_t mb, uint64_t pol) {
    asm volatile("mbarrier.arrive.expect_tx.shared.b64 _, [%0], %1;"
                 :: "r"(mb), "r"((unsigned)CHUNK) : "memory");
    asm volatile(
        "cp.async.bulk.shared::cta.global.mbarrier::complete_tx::bytes"
        ".L2::cache_hint [%0], [%1], %2, [%3], %4;"
        :: "r"(buf), "l"(g), "r"((unsigned)CHUNK), "r"(mb), "l"(pol)
        : "memory");
}

__global__ void __launch_bounds__(32) k_copy_tma(const char* __restrict__ src,
                                                 char* __restrict__ dst,
                                                 long long nch) {
    extern __shared__ __align__(128) char sm[];
    if (threadIdx.x != 0) return;
    uint32_t base = s2u(sm);
    uint32_t bufs[NBUF], mbs[NBUF];
    #pragma unroll
    for (int i = 0; i < NBUF; i++) {
        bufs[i] = base + i * CHUNK;
        mbs[i]  = base + NBUF * CHUNK + i * 8;
        asm volatile("mbarrier.init.shared.b64 [%0], 1;" :: "r"(mbs[i])
                     : "memory");
    }
    asm volatile("fence.proxy.async.shared::cta;" ::: "memory");

    uint64_t pol;
    asm volatile("createpolicy.fractional.L2::evict_first.b64 %0, 1.0;"
                 : "=l"(pol));

    long long step = gridDim.x;
    long long c0 = blockIdx.x;
    if (c0 >= nch) return;
    long long nloc = (nch - c0 + step - 1) / step;
    int ph[NBUF] = {0, 0, 0, 0};

    // prologue: 2 loads in flight
    tma_load(bufs[0], src + c0 * CHUNK, mbs[0], pol);
    if (nloc > 1) tma_load(bufs[1], src + (c0 + step) * CHUNK, mbs[1], pol);

    for (long long k = 0; k < nloc; k++) {
        int s = (int)(k & (NBUF - 1));
        asm volatile(
            "{\n\t.reg .pred p;\n"
            "WL_%=:\n\t"
            "mbarrier.try_wait.parity.shared.b64 p, [%0], %1;\n\t"
            "@p bra WD_%=;\n\t"
            "bra WL_%=;\n"
            "WD_%=:\n\t}"
            :: "r"(mbs[s]), "r"((unsigned)ph[s]) : "memory");
        ph[s] ^= 1;

        asm volatile(
            "cp.async.bulk.global.shared::cta.bulk_group.L2::cache_hint "
            "[%0], [%1], %2, %3;"
            :: "l"(dst + (c0 + k * step) * CHUNK), "r"(bufs[s]),
               "r"((unsigned)CHUNK), "l"(pol) : "memory");
        asm volatile("cp.async.bulk.commit_group;" ::: "memory");
        // allow 2 stores outstanding; buffer (k+2)%4's prior store (iter k-2)
        // is guaranteed drained before we reload it below.
        asm volatile("cp.async.bulk.wait_group.read 2;" ::: "memory");

        long long kn = k + 2;
        if (kn < nloc)
            tma_load(bufs[(int)(kn & (NBUF - 1))],
                     src + (c0 + kn * step) * CHUNK,
                     mbs[(int)(kn & (NBUF - 1))], pol);
    }
    asm volatile("cp.async.bulk.wait_group 0;" ::: "memory");
}

// ---------------- K6: build x, LN0, 3-layer MLP, LNf -> g_hout --------------
__global__ void k_mlp_compute(const float* __restrict__ nf,
                              const float* __restrict__ wp,
                              const float* __restrict__ mp,
                              const int* __restrict__ ridx,
                              const float* __restrict__ ln0s, const float* __restrict__ ln0b,
                              const float* __restrict__ w1, const float* __restrict__ b1,
                              const float* __restrict__ w2, const float* __restrict__ b2,
                              const float* __restrict__ w3, const float* __restrict__ b3,
                              const float* __restrict__ lnfs, const float* __restrict__ lnfb) {
    __shared__ float xs[17];
    __shared__ float h[DH];
    __shared__ float red1[4], red2[4];
    __shared__ float s_mu, s_rs;
    int j = threadIdx.x;
    int idx = ridx[blockIdx.x];

    if (j < 17) {
        float v;
        if (j < 9)       v = g_sums[j % 3];
        else if (j < 12) v = nf[(size_t)idx * 12 + (j - 9)];
        else if (j < 15) v = wp[(size_t)idx * 3 + (j - 12)] - g_sums[3 + (j - 12)];
        else             v = mp[(size_t)idx * 2 + (j - 15)] - g_sums[6 + (j - 15)];
        xs[j] = v;
    }
    __syncthreads();
    if (j == 0) {
        float mu = 0.f;
        for (int k = 0; k < 17; k++) mu += xs[k];
        mu /= 17.f;
        float var = 0.f;
        for (int k = 0; k < 17; k++) { float d = xs[k] - mu; var += d * d; }
        var /= 17.f;
        s_mu = mu; s_rs = rsqrtf(var + EPS);
    }
    __syncthreads();
    if (j < 17) xs[j] = (xs[j] - s_mu) * s_rs * ln0s[j] + ln0b[j];
    __syncthreads();

    float acc = b1[j];
    #pragma unroll
    for (int k = 0; k < 17; k++) acc = fmaf(xs[k], w1[k * DH + j], acc);
    acc = fmaxf(acc, 0.f);
    h[j] = acc;
    __syncthreads();

    acc = b2[j];
    #pragma unroll 8
    for (int k = 0; k < DH; k++) acc = fmaf(h[k], w2[k * DH + j], acc);
    acc = fmaxf(acc, 0.f);
    __syncthreads();
    h[j] = acc;
    __syncthreads();

    acc = b3[j];
    #pragma unroll 8
    for (int k = 0; k < DH; k++) acc = fmaf(h[k], w3[k * DH + j], acc);

    float s1 = acc, s2 = acc * acc;
    #pragma unroll
    for (int o = 16; o; o >>= 1) {
        s1 += __shfl_xor_sync(0xFFFFFFFFu, s1, o);
        s2 += __shfl_xor_sync(0xFFFFFFFFu, s2, o);
    }
    if ((j & 31) == 0) { red1[j >> 5] = s1; red2[j >> 5] = s2; }
    __syncthreads();
    float mu = (red1[0] + red1[1] + red1[2] + red1[3]) * (1.f / 128.f);
    float m2 = (red2[0] + red2[1] + red2[2] + red2[3]) * (1.f / 128.f);
    float var = m2 - mu * mu;
    g_hout[blockIdx.x][j] = (acc - mu) * rsqrtf(var + EPS) * lnfs[j] + lnfb[j];
}

// ---------------- K7: tiny tail — out[ridx] += g_hout -----------------------
__global__ void k_add(const int* __restrict__ ridx, float* __restrict__ out) {
    int j = threadIdx.x;
    int idx = ridx[blockIdx.x];
    out[(size_t)idx * DH + j] += g_hout[blockIdx.x][j];
}

// ---------------- launch ----------------------------------------------------
extern "C" void kernel_launch(void* const* d_in, const int* in_sizes, int n_in,
                              void* d_out, int out_size) {
    const float* nf   = (const float*)d_in[0];
    const float* wp   = (const float*)d_in[1];
    const float* mp   = (const float*)d_in[2];
    const float* lat  = (const float*)d_in[3];
    const int*   ridx = (const int*)  d_in[4];
    const float* ln0s = (const float*)d_in[5];
    const float* ln0b = (const float*)d_in[6];
    const float* w1   = (const float*)d_in[7];
    const float* b1   = (const float*)d_in[8];
    const float* w2   = (const float*)d_in[9];
    const float* b2   = (const float*)d_in[10];
    const float* w3   = (const float*)d_in[11];
    const float* b3   = (const float*)d_in[12];
    const float* lnfs = (const float*)d_in[13];
    const float* lnfb = (const float*)d_in[14];
    float* out = (float*)d_out;
    int S = in_sizes[4];

    static cudaStream_t s_side = nullptr;
    static cudaEvent_t  s_fork = nullptr, s_join = nullptr;
    if (s_side == nullptr) {
        cudaStreamCreateWithFlags(&s_side, cudaStreamNonBlocking);
        cudaEventCreateWithFlags(&s_fork, cudaEventDisableTiming);
        cudaEventCreateWithFlags(&s_join, cudaEventDisableTiming);
        cudaFuncSetAttribute(k_copy_tma,
                             cudaFuncAttributeMaxDynamicSharedMemorySize,
                             COPY_SMEM);
    }

    cudaEventRecord(s_fork, 0);
    cudaStreamWaitEvent(s_side, s_fork, 0);

    // Side stream: selection chain + full MLP compute (hidden under the copy).
    k_zero<<<(NB + 255) / 256, 256, 0, s_side>>>();
    k_speed2_hist<<<296, 512, 0, s_side>>>(nf);
    k_find_bucket<<<1, 1024, 0, s_side>>>();
    k_sum_and_cand<<<296, 512, 0, s_side>>>(nf, wp, mp);
    k_finalize<<<1, 256, 0, s_side>>>(nf, wp, mp);
    k_mlp_compute<<<S, DH, 0, s_side>>>(nf, wp, mp, ridx, ln0s, ln0b,
                                        w1, b1, w2, b2, w3, b3, lnfs, lnfb);
    cudaEventRecord(s_join, s_side);

    // Main stream: all-TMA copy (512e6 bytes = 31250 x 16KB chunks exactly).
    long long total = (long long)NN * DH * sizeof(float);
    k_copy_tma<<<COPY_GRID, 32, COPY_SMEM>>>((const char*)lat, (char*)out,
                                             total / CHUNK);

    // Tail: only the 60-row add remains after the copy.
    cudaStreamWaitEvent(0, s_join, 0);
    k_add<<<S, DH>>>(ridx, out);
}